// round 15
// baseline (speedup 1.0000x reference)
#include <cuda_runtime.h>
#include <cuda_bf16.h>
#include <cstdint>
#include <math.h>

#define NB 8
#define NN 1024
#define NH 8
#define SCALE_F 0.08838834764831845f  // 128^-0.5

// ---------------- scratch (device globals; no cudaMalloc allowed) ----------
__device__ float g_sm [64ull * 1024 * 1024];  // fp32 [b*h][i][j] raw m-scores
__device__ float g_pmax[64ull * 1024 * 8];    // per-row per-ntile partial max
__device__ float g_psum[64ull * 1024 * 8];    // partial sumexp (vs local max)

// bf16 split planes (hi / lo)
__device__ __nv_bfloat16 g_svh[8ull * 1024 * 1024];     // s_v split
__device__ __nv_bfloat16 g_svl[8ull * 1024 * 1024];
__device__ __nv_bfloat16 g_smh_in[8ull * 1024 * 1024];  // s_m split
__device__ __nv_bfloat16 g_sml_in[8ull * 1024 * 1024];
__device__ __nv_bfloat16 g_wqkvh[3072ull * 1024];       // W_qkv^T
__device__ __nv_bfloat16 g_wqkvl[3072ull * 1024];
__device__ __nv_bfloat16 g_wqkh[2048ull * 1024];        // W_qk^T
__device__ __nv_bfloat16 g_wqkl[2048ull * 1024];
__device__ __nv_bfloat16 g_wouth[1024ull * 1024];       // W_out^T
__device__ __nv_bfloat16 g_woutl[1024ull * 1024];
__device__ __nv_bfloat16 g_qkh[8ull * 1024 * 2048];     // q_m|k_m split
__device__ __nv_bfloat16 g_qkl[8ull * 1024 * 2048];
__device__ __nv_bfloat16 g_qvh[8ull * 1024 * 3072];     // q_v|k_v|v split
__device__ __nv_bfloat16 g_qvl[8ull * 1024 * 3072];
__device__ __nv_bfloat16 g_aoh[8ull * 1024 * 1024];     // attn out split
__device__ __nv_bfloat16 g_aol[8ull * 1024 * 1024];

// ======================= helpers ===========================================
__device__ __forceinline__ uint32_t smem_u32(const void* p) {
    uint32_t a;
    asm("{ .reg .u64 t; cvta.to.shared.u64 t, %1; cvt.u32.u64 %0, t; }"
        : "=r"(a) : "l"(p));
    return a;
}
__device__ __forceinline__ void ldsm4(uint32_t* r, uint32_t addr) {
    asm volatile("ldmatrix.sync.aligned.m8n8.x4.shared.b16 {%0,%1,%2,%3}, [%4];"
                 : "=r"(r[0]), "=r"(r[1]), "=r"(r[2]), "=r"(r[3]) : "r"(addr));
}
__device__ __forceinline__ void ldsm4t(uint32_t* r, uint32_t addr) {
    asm volatile("ldmatrix.sync.aligned.m8n8.x4.trans.shared.b16 {%0,%1,%2,%3}, [%4];"
                 : "=r"(r[0]), "=r"(r[1]), "=r"(r[2]), "=r"(r[3]) : "r"(addr));
}
__device__ __forceinline__ void mma16816(float* d, const uint32_t* a, const uint32_t* b) {
    asm volatile(
        "mma.sync.aligned.m16n8k16.row.col.f32.bf16.bf16.f32 "
        "{%0,%1,%2,%3}, {%4,%5,%6,%7}, {%8,%9}, {%0,%1,%2,%3};"
        : "+f"(d[0]), "+f"(d[1]), "+f"(d[2]), "+f"(d[3])
        : "r"(a[0]), "r"(a[1]), "r"(a[2]), "r"(a[3]), "r"(b[0]), "r"(b[1]));
}
__device__ __forceinline__ uint32_t sw_off(uint32_t off) {      // 128B rows
    return off ^ ((off >> 3) & 0x70);
}
__device__ __forceinline__ uint32_t sw64(uint32_t off) {        // 64B rows
    return off ^ ((off >> 3) & 0x30);
}

// ---- fast bf16 split: truncated hi via PRMT + packed lo cvt ----
__device__ __forceinline__ uint32_t prmt_hi2(uint32_t a, uint32_t b) {
    uint32_t r;
    asm("prmt.b32 %0, %1, %2, 0x7632;" : "=r"(r) : "r"(a), "r"(b));
    return r;
}
__device__ __forceinline__ uint32_t cvt_bf2(float lo_lo, float lo_hi) {
    uint32_t r;
    asm("cvt.rn.bf16x2.f32 %0, %1, %2;" : "=r"(r) : "f"(lo_hi), "f"(lo_lo));
    return r;
}
__device__ __forceinline__ void packPair(float a, float b, uint32_t& hi, uint32_t& lo) {
    uint32_t ua = __float_as_uint(a), ub = __float_as_uint(b);
    hi = prmt_hi2(ua, ub);
    float ha = __uint_as_float(ua & 0xFFFF0000u);
    float hb = __uint_as_float(ub & 0xFFFF0000u);
    lo = cvt_bf2(a - ha, b - hb);
}
__device__ __forceinline__ void split4(const float4& v, uint32_t& h01, uint32_t& h23,
                                       uint32_t& l01, uint32_t& l23) {
    packPair(v.x, v.y, h01, l01);
    packPair(v.z, v.w, h23, l23);
}

#define CP16(dst, src) \
    asm volatile("cp.async.cg.shared.global [%0], [%1], 16;" \
                 :: "r"(dst), "l"(__cvta_generic_to_global(src)))
#define CP_COMMIT() asm volatile("cp.async.commit_group;" ::: "memory")
#define CP_WAIT1()  asm volatile("cp.async.wait_group 1;" ::: "memory")
#define CP_WAIT0()  asm volatile("cp.async.wait_group 0;" ::: "memory")

// ======================= conversion kernels ================================
// both activations in one launch: [0,2048) -> s_v, [2048,4096) -> s_m
__global__ __launch_bounds__(512) void asplit2(
    const float4* __restrict__ in1, uint2* __restrict__ oh1, uint2* __restrict__ ol1,
    const float4* __restrict__ in2, uint2* __restrict__ oh2, uint2* __restrict__ ol2,
    int n4)
{
    const int half = blockIdx.x >= 2048;
    const float4* in = half ? in2 : in1;
    uint2* oh = half ? oh2 : oh1;
    uint2* ol = half ? ol2 : ol1;
    for (int i = (blockIdx.x & 2047) * 512 + threadIdx.x; i < n4; i += 2048 * 512) {
        float4 v = in[i];
        uint32_t h01, h23, l01, l23;
        split4(v, h01, h23, l01, l23);
        oh[i] = make_uint2(h01, h23);
        ol[i] = make_uint2(l01, l23);
    }
}

// fused transpose+split of all three weights
__global__ __launch_bounds__(256) void wsplit_all(
    const float* __restrict__ Wqkv, const float* __restrict__ Wqk,
    const float* __restrict__ Wout)
{
    __shared__ float t[32][33];
    const float* W;
    __nv_bfloat16 *Th, *Tl;
    int Nd, bx = blockIdx.x;
    if (bx < 96)       { W = Wqkv; Th = g_wqkvh; Tl = g_wqkvl; Nd = 3072; }
    else if (bx < 160) { W = Wqk;  Th = g_wqkh;  Tl = g_wqkl;  Nd = 2048; bx -= 96; }
    else               { W = Wout; Th = g_wouth; Tl = g_woutl; Nd = 1024; bx -= 160; }
    const int Kd = 1024;
    const int n0 = bx * 32, k0 = blockIdx.y * 32;
    const int tx = threadIdx.x & 31, ty = threadIdx.x >> 5;
#pragma unroll
    for (int i = 0; i < 32; i += 8)
        t[ty + i][tx] = W[(size_t)(k0 + ty + i) * Nd + n0 + tx];
    __syncthreads();
#pragma unroll
    for (int i = 0; i < 32; i += 8) {
        float v = t[tx][ty + i];
        uint32_t uv = __float_as_uint(v);
        float hv = __uint_as_float(uv & 0xFFFF0000u);
        size_t o = (size_t)(n0 + ty + i) * Kd + k0 + tx;
        Th[o] = __ushort_as_bfloat16((unsigned short)(uv >> 16));
        Tl[o] = __float2bfloat16(v - hv);
    }
}

// ======================= pipelined bf16 mma.sync GEMM ======================
#define ST_BYTES  32768
#define NSTAGE    3
#define GEMM_SMEM (1024 + NSTAGE * ST_BYTES)

template<int EPI>
__global__ __launch_bounds__(256, 2) void gemm_bf16(
    const __nv_bfloat16* __restrict__ Ah, const __nv_bfloat16* __restrict__ Al,
    int lda, size_t Azb, size_t Azh,
    const __nv_bfloat16* __restrict__ Bh, const __nv_bfloat16* __restrict__ Bl,
    int ldb, size_t Bzb, size_t Bzh,
    float* __restrict__ C, __nv_bfloat16* __restrict__ Ch,
    __nv_bfloat16* __restrict__ Cl,
    int ldc, size_t Cz, int K, const float* __restrict__ bias)
{
    extern __shared__ char smraw[];
    uint32_t raw = smem_u32(smraw);
    char* sm = smraw + ((1024u - (raw & 1023u)) & 1023u);
    const uint32_t smb = smem_u32(sm);

    const int tid = threadIdx.x;
    const int wid = tid >> 5, lane = tid & 31;
    const int wm = wid & 3, wn = wid >> 2;
    const int bm = blockIdx.y * 128;
    const int z = blockIdx.z;

    int bn = blockIdx.x * 128;
    const __nv_bfloat16 *xAh = Ah, *xAl = Al, *xBh = Bh, *xBl = Bl;
    __nv_bfloat16 *xCh = Ch, *xCl = Cl;
    int xldc = ldc;
    if (EPI == 5) {
        if (blockIdx.x < 24) {
            xAh = g_svh; xAl = g_svl;
            xBh = g_wqkvh; xBl = g_wqkvl;
            xCh = g_qvh; xCl = g_qvl;
            xldc = 3072; bn = blockIdx.x * 128;
        } else {
            xAh = g_smh_in; xAl = g_sml_in;
            xBh = g_wqkh; xBl = g_wqkl;
            xCh = g_qkh; xCl = g_qkl;
            xldc = 2048; bn = (blockIdx.x - 24) * 128;
        }
    }

    const size_t zao = (size_t)(z >> 3) * Azb + (size_t)(z & 7) * Azh;
    const size_t zbo = (size_t)(z >> 3) * Bzb + (size_t)(z & 7) * Bzh;

    const __nv_bfloat16* pls[4] = {
        xAh + zao + (size_t)bm * lda, xAl + zao + (size_t)bm * lda,
        xBh + zbo + (size_t)bn * ldb, xBl + zbo + (size_t)bn * ldb };

    const int nchunks = K >> 5;

    const int cp_p = tid >> 6, cp_tp = tid & 63;
    const int cp_row0 = cp_tp >> 2, cp_c16 = cp_tp & 3;
    const int cp_ld = (cp_p < 2) ? lda : ldb;
    const __nv_bfloat16* cp_gbase = pls[cp_p] + (size_t)cp_row0 * cp_ld + cp_c16 * 8;
    const size_t cp_gstep = (size_t)16 * cp_ld;
    const uint32_t cp_sbase = (uint32_t)(cp_p * 8192) + sw64(cp_row0 * 64 + cp_c16 * 16);

#define ISSUE_STAGE(cc_) do {                                                  \
        int _c = (cc_);                                                        \
        if (_c < nchunks) {                                                    \
            uint32_t sb = smb + (uint32_t)(_c % NSTAGE) * ST_BYTES + cp_sbase; \
            const __nv_bfloat16* g = cp_gbase + ((size_t)_c << 5);             \
            _Pragma("unroll")                                                  \
            for (int i = 0; i < 8; ++i)                                        \
                CP16(sb + i * 1024, g + (size_t)i * cp_gstep);                 \
        }                                                                      \
        CP_COMMIT();                                                           \
    } while (0)

    float acc[2][8][4];
#pragma unroll
    for (int mt = 0; mt < 2; mt++)
#pragma unroll
        for (int nt = 0; nt < 8; nt++)
#pragma unroll
            for (int i = 0; i < 4; i++) acc[mt][nt][i] = 0.f;

    ISSUE_STAGE(0);
    ISSUE_STAGE(1);

    const uint32_t arow0 = wm * 32 + (lane & 15);
    const uint32_t akhalf = (lane >> 4) * 16;
    const uint32_t bg = lane >> 3, br = lane & 7;
    const uint32_t brow0 = wn * 64 + (bg >> 1) * 8 + br;
    const uint32_t bkhalf = (bg & 1) * 16;

    for (int c = 0; c < nchunks; ++c) {
        CP_WAIT1();
        __syncthreads();
        ISSUE_STAGE(c + 2);

        const uint32_t so = smb + (uint32_t)(c % NSTAGE) * ST_BYTES;
        const uint32_t aHb = so, aLb = so + 8192;
        const uint32_t bHb = so + 16384, bLb = so + 24576;

        uint32_t aH[2][2][4], aL[2][2][4];
#pragma unroll
        for (int k16 = 0; k16 < 2; ++k16)
#pragma unroll
            for (int mt = 0; mt < 2; mt++) {
                uint32_t off = sw64((arow0 + mt * 16) * 64 + k16 * 32 + akhalf);
                ldsm4(aH[k16][mt], aHb + off);
                ldsm4(aL[k16][mt], aLb + off);
            }

        uint32_t bH[2][4], bL[2][4];
        {
            uint32_t off0 = sw64(brow0 * 64 + bkhalf);
            ldsm4(bH[0], bHb + off0);
            ldsm4(bL[0], bLb + off0);
        }
#pragma unroll
        for (int s = 0; s < 8; ++s) {
            const int cur = s & 1, nxt = cur ^ 1;
            if (s < 7) {
                const int s1 = s + 1;
                uint32_t off = sw64((brow0 + (s1 & 3) * 16) * 64 +
                                    (s1 >> 2) * 32 + bkhalf);
                ldsm4(bH[nxt], bHb + off);
                ldsm4(bL[nxt], bLb + off);
            }
            const int k16 = s >> 2, nt2 = (s & 3) * 2;
#pragma unroll
            for (int mt = 0; mt < 2; mt++) {
                mma16816(acc[mt][nt2],     aH[k16][mt], &bH[cur][0]);
                mma16816(acc[mt][nt2],     aH[k16][mt], &bL[cur][0]);
                mma16816(acc[mt][nt2],     aL[k16][mt], &bH[cur][0]);
                mma16816(acc[mt][nt2 + 1], aH[k16][mt], &bH[cur][2]);
                mma16816(acc[mt][nt2 + 1], aH[k16][mt], &bL[cur][2]);
                mma16816(acc[mt][nt2 + 1], aL[k16][mt], &bH[cur][2]);
            }
        }
    }
#undef ISSUE_STAGE
    __syncthreads();

    const int rgrp = lane >> 2, cpair = (lane & 3) * 2;
#pragma unroll
    for (int mt = 0; mt < 2; mt++) {
#pragma unroll
        for (int nt = 0; nt < 8; nt++) {
            int row0 = bm + wm * 32 + mt * 16 + rgrp;
            int col = bn + wn * 64 + nt * 8 + cpair;
            float x0 = acc[mt][nt][0], x1 = acc[mt][nt][1];
            float x2 = acc[mt][nt][2], x3 = acc[mt][nt][3];
            if (EPI == 5) {
                size_t o0 = (size_t)z * Cz + (size_t)row0 * xldc + col;
                size_t o1 = o0 + 8ull * xldc;
                uint32_t hh, ll;
                packPair(x0, x1, hh, ll);
                *(uint32_t*)(xCh + o0) = hh; *(uint32_t*)(xCl + o0) = ll;
                packPair(x2, x3, hh, ll);
                *(uint32_t*)(xCh + o1) = hh; *(uint32_t*)(xCl + o1) = ll;
            } else {
                float b0 = 0.f, b1 = 0.f;
                if (EPI == 1) { b0 = bias[col]; b1 = bias[col + 1]; }
                float2 v0, v1;
                v0.x = x0 + b0; v0.y = x1 + b1;
                v1.x = x2 + b0; v1.y = x3 + b1;
                float* Cb = C + (size_t)z * Cz;
                *(float2*)(Cb + (size_t)row0 * ldc + col) = v0;
                *(float2*)(Cb + (size_t)(row0 + 8) * ldc + col) = v1;
            }
        }
    }

    if (EPI == 4) {
        float* redm_ = (float*)sm;              // [128][2]
        float* redsu = (float*)(sm + 1024);     // [128][2]
        __syncthreads();
#pragma unroll
        for (int mt = 0; mt < 2; mt++)
#pragma unroll
            for (int hf = 0; hf < 2; hf++) {
                int lrow = wm * 32 + mt * 16 + hf * 8 + rgrp;
                float mx = -1e30f;
#pragma unroll
                for (int nt = 0; nt < 8; nt++)
                    mx = fmaxf(mx, fmaxf(acc[mt][nt][hf * 2], acc[mt][nt][hf * 2 + 1]));
                mx = fmaxf(mx, __shfl_xor_sync(~0u, mx, 1));
                mx = fmaxf(mx, __shfl_xor_sync(~0u, mx, 2));
                if ((lane & 3) == 0) redm_[lrow * 2 + wn] = mx;
            }
        __syncthreads();
#pragma unroll
        for (int mt = 0; mt < 2; mt++)
#pragma unroll
            for (int hf = 0; hf < 2; hf++) {
                int lrow = wm * 32 + mt * 16 + hf * 8 + rgrp;
                float rm = fmaxf(redm_[lrow * 2], redm_[lrow * 2 + 1]);
                float su = 0.f;
#pragma unroll
                for (int nt = 0; nt < 8; nt++)
                    su += __expf(acc[mt][nt][hf * 2] - rm) +
                          __expf(acc[mt][nt][hf * 2 + 1] - rm);
                su += __shfl_xor_sync(~0u, su, 1);
                su += __shfl_xor_sync(~0u, su, 2);
                if ((lane & 3) == 0) redsu[lrow * 2 + wn] = su;
            }
        __syncthreads();
        if (tid < 128) {
            float m2 = fmaxf(redm_[tid * 2], redm_[tid * 2 + 1]);
            float s2 = redsu[tid * 2] + redsu[tid * 2 + 1];
            size_t o = ((size_t)z * 1024 + bm + tid) * 8 + blockIdx.x;
            g_pmax[o] = m2;
            g_psum[o] = s2;
        }
    }
}

// ================= tensor-core fused flash attention =======================
// CTA: TWO 64-query tiles x head x batch, 512 threads (16 warps; warps 0-7 =
// half 0, warps 8-15 = half 1, SHARED K/V buffers). Per-wn-half local softmax.
#define Q_OFF(ih, hl, kc)  ((uint32_t)((((ih) * 4 + (hl) * 2 + (kc)) * 8192)))
#define K_OFF(buf, hl, kc) ((uint32_t)(65536 + (buf) * 32768 + ((hl) * 2 + (kc)) * 8192))
#define V_OFF(buf, hl)     ((uint32_t)(131072 + (buf) * 32768 + (hl) * 16384))
#define MH_OFF   196608   // [ih][2][128]
#define LH_OFF   198656   // [ih][2][128]
#define MI_OFF   200704   // [128]
#define IL_OFF   201216   // [128]
#define ATTN_SMEM (1024 + 201728)

__global__ __launch_bounds__(512, 1) void attn_mma(const float* __restrict__ gl)
{
    extern __shared__ char smraw[];
    uint32_t raw = smem_u32(smraw);
    char* sm = smraw + ((1024u - (raw & 1023u)) & 1023u);
    const uint32_t smb = smem_u32(sm);
    float* mi_s = (float*)(sm + MI_OFF);
    float* il_s = (float*)(sm + IL_OFF);

    const int tid = threadIdx.x, lane = tid & 31, wid = tid >> 5;
    const int ih = wid >> 3;                 // query-half
    const int hw = wid & 7;
    const int wm = hw & 3, wn = hw >> 2;
    const int bg = lane >> 3, br = lane & 7;
    const int i0 = blockIdx.x * 128, h = blockIdx.y, b = blockIdx.z;
    const int bh = b * 8 + h;

    const __nv_bfloat16* qsrc[2] = {
        g_qvh + (size_t)(b * 1024 + i0) * 3072 + h * 128,
        g_qvl + (size_t)(b * 1024 + i0) * 3072 + h * 128 };
    const __nv_bfloat16* ksrc[2] = {
        g_qvh + (size_t)(b * 1024) * 3072 + 1024 + h * 128,
        g_qvl + (size_t)(b * 1024) * 3072 + 1024 + h * 128 };
    const __nv_bfloat16* vsrc[2] = {
        g_qvh + (size_t)(b * 1024) * 3072 + 2048 + h * 128,
        g_qvl + (size_t)(b * 1024) * 3072 + 2048 + h * 128 };
    const float* Sm = g_sm + ((size_t)bh << 20);
    const float* GL = gl + ((size_t)bh << 20);

#define ISSUE_KV(j0_, buf_) do {                                               \
        _Pragma("unroll")                                                      \
        for (int i = 0; i < 4; ++i) {                                          \
            int c = tid + i * 512;                                             \
            int hl = c >> 10, rem = c & 1023;                                  \
            int row = rem >> 4, seg = rem & 15;                                \
            CP16(smb + K_OFF(buf_, hl, seg >> 3) + sw_off(row * 128 + (seg & 7) * 16), \
                 ksrc[hl] + (size_t)((j0_) + row) * 3072 + seg * 8);           \
        }                                                                      \
        _Pragma("unroll")                                                      \
        for (int i = 0; i < 4; ++i) {                                          \
            int c = tid + i * 512;                                             \
            int hl = c >> 10, rem = c & 1023;                                  \
            int row = rem >> 4, seg = rem & 15;                                \
            CP16(smb + V_OFF(buf_, hl) + (seg >> 3) * 8192 + sw_off(row * 128 + (seg & 7) * 16), \
                 vsrc[hl] + (size_t)((j0_) + row) * 3072 + seg * 8);           \
        }                                                                      \
    } while (0)

    // Q load: 128 rows (both halves), 8 iters over 512 threads
#pragma unroll
    for (int i = 0; i < 8; ++i) {
        int c = tid + i * 512;
        int hl = c >> 11, rem = c & 2047;
        int row = rem >> 4, seg = rem & 15;
        CP16(smb + Q_OFF(row >> 6, hl, seg >> 3) + sw_off((row & 63) * 128 + (seg & 7) * 16),
             qsrc[hl] + (size_t)row * 3072 + seg * 8);
    }
    ISSUE_KV(0, 0);
    CP_COMMIT();

    // ---- fold row-stat combine: this CTA owns rows [i0, i0+128) ----
    if (tid < 128) {
        const float* pm = g_pmax + ((size_t)bh * 1024 + i0 + tid) * 8;
        const float* ps = g_psum + ((size_t)bh * 1024 + i0 + tid) * 8;
        float m = pm[0];
#pragma unroll
        for (int j = 1; j < 8; ++j) m = fmaxf(m, pm[j]);
        float l = 0.f;
#pragma unroll
        for (int j = 0; j < 8; ++j) l += ps[j] * __expf(pm[j] - m);
        mi_s[tid] = m;
        il_s[tid] = 1.f / l;
    }
    __syncthreads();

    const int r0 = wm * 16 + (lane >> 2);
    const int gr0 = ih * 64 + r0;            // row within the 128-row block
    const float mi0 = mi_s[gr0], mi1 = mi_s[gr0 + 8];
    const float il0 = il_s[gr0], il1 = il_s[gr0 + 8];

    float O[16][4];
#pragma unroll
    for (int g = 0; g < 16; g++)
#pragma unroll
        for (int i = 0; i < 4; i++) O[g][i] = 0.f;
    float m_run0 = -1e30f, m_run1 = -1e30f, l_run0 = 0.f, l_run1 = 0.f;

    const uint32_t aRow = (uint32_t)(wm * 16 + (lane & 15)) * 128 + (lane >> 4) * 16;
    const uint32_t bRow0 = (uint32_t)(wn * 32 + (bg >> 1) * 8 + br) * 128 + (bg & 1) * 16;
    const uint32_t bRow1 = bRow0 + 16 * 128;
    const uint32_t vRowBase = (uint32_t)(lane & 15) * 128 + (lane >> 4) * 16;

    for (int jt = 0; jt < 16; ++jt) {
        const int j0 = jt * 64, buf = jt & 1;
        CP_WAIT0();
        __syncthreads();
        if (jt < 15) { ISSUE_KV(j0 + 64, buf ^ 1); CP_COMMIT(); }

        const int colb = j0 + wn * 32 + (lane & 3) * 2;
        float2 smv[4][2], glv[4][2];
#pragma unroll
        for (int nt = 0; nt < 4; nt++) {
            smv[nt][0] = *(const float2*)(Sm + (size_t)(i0 + gr0) * 1024 + colb + nt * 8);
            smv[nt][1] = *(const float2*)(Sm + (size_t)(i0 + gr0 + 8) * 1024 + colb + nt * 8);
            glv[nt][0] = *(const float2*)(GL + (size_t)(i0 + gr0) * 1024 + colb + nt * 8);
            glv[nt][1] = *(const float2*)(GL + (size_t)(i0 + gr0 + 8) * 1024 + colb + nt * 8);
        }

        float sc[4][4];
#pragma unroll
        for (int nt = 0; nt < 4; nt++)
#pragma unroll
            for (int i = 0; i < 4; i++) sc[nt][i] = 0.f;

#pragma unroll
        for (int s = 0; s < 8; ++s) {
            const int kc = s >> 2;
            const uint32_t kb = (uint32_t)(s & 3) * 32;
            uint32_t aH[4], aL[4];
            ldsm4(aH, smb + Q_OFF(ih, 0, kc) + sw_off(aRow + kb));
            ldsm4(aL, smb + Q_OFF(ih, 1, kc) + sw_off(aRow + kb));
            uint32_t kh01[4], kh23[4], kl01[4], kl23[4];
            ldsm4(kh01, smb + K_OFF(buf, 0, kc) + sw_off(bRow0 + kb));
            ldsm4(kh23, smb + K_OFF(buf, 0, kc) + sw_off(bRow1 + kb));
            ldsm4(kl01, smb + K_OFF(buf, 1, kc) + sw_off(bRow0 + kb));
            ldsm4(kl23, smb + K_OFF(buf, 1, kc) + sw_off(bRow1 + kb));
#pragma unroll
            for (int nt = 0; nt < 4; nt++) {
                const uint32_t* bhp = (nt < 2) ? &kh01[(nt & 1) * 2] : &kh23[(nt & 1) * 2];
                const uint32_t* blp = (nt < 2) ? &kl01[(nt & 1) * 2] : &kl23[(nt & 1) * 2];
                mma16816(sc[nt], aH, bhp);
                mma16816(sc[nt], aH, blp);
                mma16816(sc[nt], aL, bhp);
            }
        }

        // dots in-place over sc; local (per wn-half) softmax
        float mx0 = -1e30f, mx1 = -1e30f;
#pragma unroll
        for (int nt = 0; nt < 4; nt++) {
            float pm0 = __expf(smv[nt][0].x - mi0) * il0;
            float pm1 = __expf(smv[nt][0].y - mi0) * il0;
            float pm2 = __expf(smv[nt][1].x - mi1) * il1;
            float pm3 = __expf(smv[nt][1].y - mi1) * il1;
            sc[nt][0] = fmaf(pm0 * sc[nt][0], SCALE_F, glv[nt][0].x);
            sc[nt][1] = fmaf(pm1 * sc[nt][1], SCALE_F, glv[nt][0].y);
            sc[nt][2] = fmaf(pm2 * sc[nt][2], SCALE_F, glv[nt][1].x);
            sc[nt][3] = fmaf(pm3 * sc[nt][3], SCALE_F, glv[nt][1].y);
            mx0 = fmaxf(mx0, fmaxf(sc[nt][0], sc[nt][1]));
            mx1 = fmaxf(mx1, fmaxf(sc[nt][2], sc[nt][3]));
        }
        mx0 = fmaxf(mx0, __shfl_xor_sync(~0u, mx0, 1));
        mx0 = fmaxf(mx0, __shfl_xor_sync(~0u, mx0, 2));
        mx1 = fmaxf(mx1, __shfl_xor_sync(~0u, mx1, 1));
        mx1 = fmaxf(mx1, __shfl_xor_sync(~0u, mx1, 2));

        float mn0 = fmaxf(m_run0, mx0);
        float mn1 = fmaxf(m_run1, mx1);
        float al0 = __expf(m_run0 - mn0); m_run0 = mn0;
        float al1 = __expf(m_run1 - mn1); m_run1 = mn1;

        float su0 = 0.f, su1 = 0.f;
#pragma unroll
        for (int nt = 0; nt < 4; nt++) {
            sc[nt][0] = __expf(sc[nt][0] - mn0);
            sc[nt][1] = __expf(sc[nt][1] - mn0);
            sc[nt][2] = __expf(sc[nt][2] - mn1);
            sc[nt][3] = __expf(sc[nt][3] - mn1);
            su0 += sc[nt][0] + sc[nt][1];
            su1 += sc[nt][2] + sc[nt][3];
        }
        su0 += __shfl_xor_sync(~0u, su0, 1); su0 += __shfl_xor_sync(~0u, su0, 2);
        su1 += __shfl_xor_sync(~0u, su1, 1); su1 += __shfl_xor_sync(~0u, su1, 2);
        l_run0 = l_run0 * al0 + su0;
        l_run1 = l_run1 * al1 + su1;

        uint32_t aPh[2][4], aPl[2][4];
#pragma unroll
        for (int s = 0; s < 2; s++) {
            packPair(sc[2 * s][0],     sc[2 * s][1],     aPh[s][0], aPl[s][0]);
            packPair(sc[2 * s][2],     sc[2 * s][3],     aPh[s][1], aPl[s][1]);
            packPair(sc[2 * s + 1][0], sc[2 * s + 1][1], aPh[s][2], aPl[s][2]);
            packPair(sc[2 * s + 1][2], sc[2 * s + 1][3], aPh[s][3], aPl[s][3]);
        }

#pragma unroll
        for (int g = 0; g < 16; g++) {
            O[g][0] *= al0; O[g][1] *= al0;
            O[g][2] *= al1; O[g][3] *= al1;
        }

#pragma unroll
        for (int s = 0; s < 2; s++) {
            const uint32_t vro = (uint32_t)(wn * 32 + s * 16) * 128 + vRowBase;
#pragma unroll
            for (int dh = 0; dh < 2; dh++) {
#pragma unroll
                for (int c4 = 0; c4 < 4; c4++) {
                    uint32_t off = sw_off(vro + c4 * 32) + dh * 8192;
                    uint32_t vH[4], vL[4];
                    ldsm4t(vH, smb + V_OFF(buf, 0) + off);
                    ldsm4t(vL, smb + V_OFF(buf, 1) + off);
                    const int g = dh * 8 + c4 * 2;
                    mma16816(O[g],     aPh[s], &vH[0]);
                    mma16816(O[g],     aPh[s], &vL[0]);
                    mma16816(O[g],     aPl[s], &vH[0]);
                    mma16816(O[g + 1], aPh[s], &vH[2]);
                    mma16816(O[g + 1], aPh[s], &vL[2]);
                    mma16816(O[g + 1], aPl[s], &vH[2]);
                }
            }
        }
    }
#undef ISSUE_KV

    // ---- merge the two wn halves within each query-half -------------------
    float* mh = (float*)(sm + MH_OFF + ih * 1024);   // [2][128]
    float* lh = (float*)(sm + LH_OFF + ih * 1024);
    __syncthreads();
    if ((lane & 3) == 0) {
        mh[wn * 128 + r0] = m_run0;     mh[wn * 128 + r0 + 8] = m_run1;
        lh[wn * 128 + r0] = l_run0;     lh[wn * 128 + r0 + 8] = l_run1;
    }
    __syncthreads();
    float sc0, sc1;
    {
        float ma = mh[r0], mb = mh[128 + r0];
        float M = fmaxf(ma, mb);
        float L = lh[r0] * __expf(ma - M) + lh[128 + r0] * __expf(mb - M);
        sc0 = __expf((wn ? mb : ma) - M) / L;
        float ma1 = mh[r0 + 8], mb1 = mh[128 + r0 + 8];
        float M1 = fmaxf(ma1, mb1);
        float L1 = lh[r0 + 8] * __expf(ma1 - M1) + lh[128 + r0 + 8] * __expf(mb1 - M1);
        sc1 = __expf((wn ? mb1 : ma1) - M1) / L1;
    }

    // half 0 reduces in dead Q region (0..), half 1 in dead K region (65536..)
    float* ored = (float*)(sm + (ih ? 65536 : 0));
    if (wn == 1) {
#pragma unroll
        for (int g = 0; g < 16; g++) {
            *(float2*)&ored[r0 * 132 + g * 8 + (lane & 3) * 2] =
                make_float2(O[g][0] * sc0, O[g][1] * sc0);
            *(float2*)&ored[(r0 + 8) * 132 + g * 8 + (lane & 3) * 2] =
                make_float2(O[g][2] * sc1, O[g][3] * sc1);
        }
    }
    __syncthreads();
    if (wn == 0) {
#pragma unroll
        for (int g = 0; g < 16; g++) {
            float2 a0 = *(float2*)&ored[r0 * 132 + g * 8 + (lane & 3) * 2];
            float2 a1 = *(float2*)&ored[(r0 + 8) * 132 + g * 8 + (lane & 3) * 2];
            float x0 = O[g][0] * sc0 + a0.x;
            float x1 = O[g][1] * sc0 + a0.y;
            float x2 = O[g][2] * sc1 + a1.x;
            float x3 = O[g][3] * sc1 + a1.y;
            uint32_t hh, ll;
            size_t off = (size_t)(b * 1024 + i0 + gr0) * 1024 + h * 128 + g * 8 + (lane & 3) * 2;
            packPair(x0, x1, hh, ll);
            *(uint32_t*)(g_aoh + off) = hh; *(uint32_t*)(g_aol + off) = ll;
            packPair(x2, x3, hh, ll);
            *(uint32_t*)(g_aoh + off + 8 * 1024) = hh;
            *(uint32_t*)(g_aol + off + 8 * 1024) = ll;
        }
    }
}

// ---------------- launch ----------------------------------------------------
extern "C" void kernel_launch(void* const* d_in, const int* in_sizes, int n_in,
                              void* d_out, int out_size)
{
    const float* s_v   = (const float*)d_in[0];
    const float* s_m   = (const float*)d_in[1];
    const float* g_l   = (const float*)d_in[2];
    const float* W_qkv = (const float*)d_in[3];
    const float* W_qk  = (const float*)d_in[4];
    const float* W_out = (const float*)d_in[5];
    const float* b_out = (const float*)d_in[6];
    float* out = (float*)d_out;

    float* p_sm;
    __nv_bfloat16 *p_svh, *p_svl, *p_smh, *p_sml;
    __nv_bfloat16 *p_wouth, *p_woutl, *p_qkh, *p_qkl, *p_aoh, *p_aol;
    cudaGetSymbolAddress((void**)&p_sm,  g_sm);
    cudaGetSymbolAddress((void**)&p_svh, g_svh);
    cudaGetSymbolAddress((void**)&p_svl, g_svl);
    cudaGetSymbolAddress((void**)&p_smh, g_smh_in);
    cudaGetSymbolAddress((void**)&p_sml, g_sml_in);
    cudaGetSymbolAddress((void**)&p_wouth, g_wouth);
    cudaGetSymbolAddress((void**)&p_woutl, g_woutl);
    cudaGetSymbolAddress((void**)&p_qkh, g_qkh);
    cudaGetSymbolAddress((void**)&p_qkl, g_qkl);
    cudaGetSymbolAddress((void**)&p_aoh, g_aoh);
    cudaGetSymbolAddress((void**)&p_aol, g_aol);

    cudaFuncSetAttribute(gemm_bf16<1>, cudaFuncAttributeMaxDynamicSharedMemorySize, GEMM_SMEM);
    cudaFuncSetAttribute(gemm_bf16<4>, cudaFuncAttributeMaxDynamicSharedMemorySize, GEMM_SMEM);
    cudaFuncSetAttribute(gemm_bf16<5>, cudaFuncAttributeMaxDynamicSharedMemorySize, GEMM_SMEM);
    cudaFuncSetAttribute(attn_mma, cudaFuncAttributeMaxDynamicSharedMemorySize, ATTN_SMEM);

    // [0] both activation splits in one launch
    asplit2<<<4096, 512>>>((const float4*)s_v, (uint2*)p_svh, (uint2*)p_svl,
                           (const float4*)s_m, (uint2*)p_smh, (uint2*)p_sml,
                           8 * 1024 * 1024 / 4);
    // [1] fused weight transpose+split
    wsplit_all<<<dim3(192, 32), 256>>>(W_qkv, W_qk, W_out);
    // [2] FUSED QKV + QK projections
    gemm_bf16<5><<<dim3(40, 64, 1), 256, GEMM_SMEM>>>(
        p_svh, p_svl, 1024, 0, 0, nullptr, nullptr, 1024, 0, 0,
        nullptr, nullptr, nullptr, 3072, 0, 1024, nullptr);
    // [3] m-stream scores per (b,h) -> fp32 g_sm + fused row-stat partials
    gemm_bf16<4><<<dim3(8, 8, 64), 256, GEMM_SMEM>>>(
        p_qkh, p_qkl, 2048, (size_t)NN * 2048, 128,
        p_qkh + 1024, p_qkl + 1024, 2048, (size_t)NN * 2048, 128,
        p_sm, nullptr, nullptr, 1024, (size_t)NN * NN, 128, nullptr);
    // [4] tensor-core fused attention (two query-halves per CTA, shared K/V)
    attn_mma<<<dim3(8, NH, NB), 512, ATTN_SMEM>>>(g_l);
    // [5] output projection + bias -> out
    gemm_bf16<1><<<dim3(8, 64, 1), 256, GEMM_SMEM>>>(
        p_aoh, p_aol, 1024, 0, 0, p_wouth, p_woutl, 1024, 0, 0,
        out, nullptr, nullptr, 1024, 0, 1024, b_out);
}

// round 16
// speedup vs baseline: 1.0363x; 1.0363x over previous
#include <cuda_runtime.h>
#include <cuda_bf16.h>
#include <cstdint>
#include <math.h>

#define NB 8
#define NN 1024
#define NH 8
#define SCALE_F 0.08838834764831845f  // 128^-0.5

// ---------------- scratch (device globals; no cudaMalloc allowed) ----------
__device__ float g_sm [64ull * 1024 * 1024];  // fp32 [b*h][i][j] raw m-scores
__device__ float g_pmax[64ull * 1024 * 8];    // per-row per-ntile partial max
__device__ float g_psum[64ull * 1024 * 8];    // partial sumexp (vs local max)

// bf16 split planes (hi / lo)
__device__ __nv_bfloat16 g_svh[8ull * 1024 * 1024];     // s_v split
__device__ __nv_bfloat16 g_svl[8ull * 1024 * 1024];
__device__ __nv_bfloat16 g_smh_in[8ull * 1024 * 1024];  // s_m split
__device__ __nv_bfloat16 g_sml_in[8ull * 1024 * 1024];
__device__ __nv_bfloat16 g_wqkvh[3072ull * 1024];       // W_qkv^T
__device__ __nv_bfloat16 g_wqkvl[3072ull * 1024];
__device__ __nv_bfloat16 g_wqkh[2048ull * 1024];        // W_qk^T
__device__ __nv_bfloat16 g_wqkl[2048ull * 1024];
__device__ __nv_bfloat16 g_wouth[1024ull * 1024];       // W_out^T
__device__ __nv_bfloat16 g_woutl[1024ull * 1024];
__device__ __nv_bfloat16 g_qkh[8ull * 1024 * 2048];     // q_m|k_m split
__device__ __nv_bfloat16 g_qkl[8ull * 1024 * 2048];
__device__ __nv_bfloat16 g_qvh[8ull * 1024 * 3072];     // q_v|k_v|v split
__device__ __nv_bfloat16 g_qvl[8ull * 1024 * 3072];
__device__ __nv_bfloat16 g_aoh[8ull * 1024 * 1024];     // attn out split
__device__ __nv_bfloat16 g_aol[8ull * 1024 * 1024];

// ======================= helpers ===========================================
__device__ __forceinline__ uint32_t smem_u32(const void* p) {
    uint32_t a;
    asm("{ .reg .u64 t; cvta.to.shared.u64 t, %1; cvt.u32.u64 %0, t; }"
        : "=r"(a) : "l"(p));
    return a;
}
__device__ __forceinline__ void ldsm4(uint32_t* r, uint32_t addr) {
    asm volatile("ldmatrix.sync.aligned.m8n8.x4.shared.b16 {%0,%1,%2,%3}, [%4];"
                 : "=r"(r[0]), "=r"(r[1]), "=r"(r[2]), "=r"(r[3]) : "r"(addr));
}
__device__ __forceinline__ void ldsm4t(uint32_t* r, uint32_t addr) {
    asm volatile("ldmatrix.sync.aligned.m8n8.x4.trans.shared.b16 {%0,%1,%2,%3}, [%4];"
                 : "=r"(r[0]), "=r"(r[1]), "=r"(r[2]), "=r"(r[3]) : "r"(addr));
}
__device__ __forceinline__ void mma16816(float* d, const uint32_t* a, const uint32_t* b) {
    asm volatile(
        "mma.sync.aligned.m16n8k16.row.col.f32.bf16.bf16.f32 "
        "{%0,%1,%2,%3}, {%4,%5,%6,%7}, {%8,%9}, {%0,%1,%2,%3};"
        : "+f"(d[0]), "+f"(d[1]), "+f"(d[2]), "+f"(d[3])
        : "r"(a[0]), "r"(a[1]), "r"(a[2]), "r"(a[3]), "r"(b[0]), "r"(b[1]));
}
__device__ __forceinline__ uint32_t sw_off(uint32_t off) {      // 128B rows
    return off ^ ((off >> 3) & 0x70);
}
__device__ __forceinline__ uint32_t sw64(uint32_t off) {        // 64B rows
    return off ^ ((off >> 3) & 0x30);
}

// ---- fast bf16 split: truncated hi via PRMT + packed lo cvt ----
__device__ __forceinline__ uint32_t prmt_hi2(uint32_t a, uint32_t b) {
    uint32_t r;
    asm("prmt.b32 %0, %1, %2, 0x7632;" : "=r"(r) : "r"(a), "r"(b));
    return r;
}
__device__ __forceinline__ uint32_t cvt_bf2(float lo_lo, float lo_hi) {
    uint32_t r;
    asm("cvt.rn.bf16x2.f32 %0, %1, %2;" : "=r"(r) : "f"(lo_hi), "f"(lo_lo));
    return r;
}
__device__ __forceinline__ void packPair(float a, float b, uint32_t& hi, uint32_t& lo) {
    uint32_t ua = __float_as_uint(a), ub = __float_as_uint(b);
    hi = prmt_hi2(ua, ub);
    float ha = __uint_as_float(ua & 0xFFFF0000u);
    float hb = __uint_as_float(ub & 0xFFFF0000u);
    lo = cvt_bf2(a - ha, b - hb);
}
__device__ __forceinline__ void split4(const float4& v, uint32_t& h01, uint32_t& h23,
                                       uint32_t& l01, uint32_t& l23) {
    packPair(v.x, v.y, h01, l01);
    packPair(v.z, v.w, h23, l23);
}

#define CP16(dst, src) \
    asm volatile("cp.async.cg.shared.global [%0], [%1], 16;" \
                 :: "r"(dst), "l"(__cvta_generic_to_global(src)))
#define CP_COMMIT() asm volatile("cp.async.commit_group;" ::: "memory")
#define CP_WAIT1()  asm volatile("cp.async.wait_group 1;" ::: "memory")
#define CP_WAIT0()  asm volatile("cp.async.wait_group 0;" ::: "memory")

// ======================= fused preprocessing ===============================
// ONE launch: [0,8192) activation splits (s_v then s_m), [8192,14336) weight
// transpose+split (W_qkv | W_qk | W_out). 256 threads.
__global__ __launch_bounds__(256) void prep_all(
    const float4* __restrict__ sv, const float4* __restrict__ smi,
    const float* __restrict__ Wqkv, const float* __restrict__ Wqk,
    const float* __restrict__ Wout)
{
    int bx = blockIdx.x;
    if (bx < 8192) {
        // activations: 4M float4 total (2M per tensor); 512 f4 per block
        const int half = bx >= 4096;
        const float4* in = half ? smi : sv;
        uint2* oh = (uint2*)(half ? g_smh_in : g_svh);
        uint2* ol = (uint2*)(half ? g_sml_in : g_svl);
        int base = (bx & 4095) * 512 + threadIdx.x;
#pragma unroll
        for (int it = 0; it < 2; ++it) {
            int i = base + it * 256;
            float4 v = in[i];
            uint32_t h01, h23, l01, l23;
            split4(v, h01, h23, l01, l23);
            oh[i] = make_uint2(h01, h23);
            ol[i] = make_uint2(l01, l23);
        }
        return;
    }
    // weights: 6144 blocks of 32x32 transpose tiles
    __shared__ float t[32][33];
    bx -= 8192;
    const int wy = bx & 31;         // k-tile (32 each)
    int wx = bx >> 5;               // n-tile index across the 3 weights
    const float* W;
    __nv_bfloat16 *Th, *Tl;
    int Nd;
    if (wx < 96)       { W = Wqkv; Th = g_wqkvh; Tl = g_wqkvl; Nd = 3072; }
    else if (wx < 160) { W = Wqk;  Th = g_wqkh;  Tl = g_wqkl;  Nd = 2048; wx -= 96; }
    else               { W = Wout; Th = g_wouth; Tl = g_woutl; Nd = 1024; wx -= 160; }
    const int Kd = 1024;
    const int n0 = wx * 32, k0 = wy * 32;
    const int tx = threadIdx.x & 31, ty = threadIdx.x >> 5;
#pragma unroll
    for (int i = 0; i < 32; i += 8)
        t[ty + i][tx] = W[(size_t)(k0 + ty + i) * Nd + n0 + tx];
    __syncthreads();
#pragma unroll
    for (int i = 0; i < 32; i += 8) {
        float v = t[tx][ty + i];
        uint32_t uv = __float_as_uint(v);
        float hv = __uint_as_float(uv & 0xFFFF0000u);
        size_t o = (size_t)(n0 + ty + i) * Kd + k0 + tx;
        Th[o] = __ushort_as_bfloat16((unsigned short)(uv >> 16));
        Tl[o] = __float2bfloat16(v - hv);
    }
}

// ======================= pipelined bf16 mma.sync GEMM ======================
#define ST_BYTES  32768
#define NSTAGE    3
#define GEMM_SMEM (1024 + NSTAGE * ST_BYTES)

template<int EPI>
__global__ __launch_bounds__(256, 2) void gemm_bf16(
    const __nv_bfloat16* __restrict__ Ah, const __nv_bfloat16* __restrict__ Al,
    int lda, size_t Azb, size_t Azh,
    const __nv_bfloat16* __restrict__ Bh, const __nv_bfloat16* __restrict__ Bl,
    int ldb, size_t Bzb, size_t Bzh,
    float* __restrict__ C, __nv_bfloat16* __restrict__ Ch,
    __nv_bfloat16* __restrict__ Cl,
    int ldc, size_t Cz, int K, const float* __restrict__ bias)
{
    extern __shared__ char smraw[];
    uint32_t raw = smem_u32(smraw);
    char* sm = smraw + ((1024u - (raw & 1023u)) & 1023u);
    const uint32_t smb = smem_u32(sm);

    const int tid = threadIdx.x;
    const int wid = tid >> 5, lane = tid & 31;
    const int wm = wid & 3, wn = wid >> 2;
    const int bm = blockIdx.y * 128;
    const int z = blockIdx.z;

    int bn = blockIdx.x * 128;
    const __nv_bfloat16 *xAh = Ah, *xAl = Al, *xBh = Bh, *xBl = Bl;
    __nv_bfloat16 *xCh = Ch, *xCl = Cl;
    int xldc = ldc;
    if (EPI == 5) {
        if (blockIdx.x < 24) {
            xAh = g_svh; xAl = g_svl;
            xBh = g_wqkvh; xBl = g_wqkvl;
            xCh = g_qvh; xCl = g_qvl;
            xldc = 3072; bn = blockIdx.x * 128;
        } else {
            xAh = g_smh_in; xAl = g_sml_in;
            xBh = g_wqkh; xBl = g_wqkl;
            xCh = g_qkh; xCl = g_qkl;
            xldc = 2048; bn = (blockIdx.x - 24) * 128;
        }
    }

    const size_t zao = (size_t)(z >> 3) * Azb + (size_t)(z & 7) * Azh;
    const size_t zbo = (size_t)(z >> 3) * Bzb + (size_t)(z & 7) * Bzh;

    const __nv_bfloat16* pls[4] = {
        xAh + zao + (size_t)bm * lda, xAl + zao + (size_t)bm * lda,
        xBh + zbo + (size_t)bn * ldb, xBl + zbo + (size_t)bn * ldb };

    const int nchunks = K >> 5;

    const int cp_p = tid >> 6, cp_tp = tid & 63;
    const int cp_row0 = cp_tp >> 2, cp_c16 = cp_tp & 3;
    const int cp_ld = (cp_p < 2) ? lda : ldb;
    const __nv_bfloat16* cp_gbase = pls[cp_p] + (size_t)cp_row0 * cp_ld + cp_c16 * 8;
    const size_t cp_gstep = (size_t)16 * cp_ld;
    const uint32_t cp_sbase = (uint32_t)(cp_p * 8192) + sw64(cp_row0 * 64 + cp_c16 * 16);

#define ISSUE_STAGE(cc_) do {                                                  \
        int _c = (cc_);                                                        \
        if (_c < nchunks) {                                                    \
            uint32_t sb = smb + (uint32_t)(_c % NSTAGE) * ST_BYTES + cp_sbase; \
            const __nv_bfloat16* g = cp_gbase + ((size_t)_c << 5);             \
            _Pragma("unroll")                                                  \
            for (int i = 0; i < 8; ++i)                                        \
                CP16(sb + i * 1024, g + (size_t)i * cp_gstep);                 \
        }                                                                      \
        CP_COMMIT();                                                           \
    } while (0)

    float acc[2][8][4];
#pragma unroll
    for (int mt = 0; mt < 2; mt++)
#pragma unroll
        for (int nt = 0; nt < 8; nt++)
#pragma unroll
            for (int i = 0; i < 4; i++) acc[mt][nt][i] = 0.f;

    ISSUE_STAGE(0);
    ISSUE_STAGE(1);

    const uint32_t arow0 = wm * 32 + (lane & 15);
    const uint32_t akhalf = (lane >> 4) * 16;
    const uint32_t bg = lane >> 3, br = lane & 7;
    const uint32_t brow0 = wn * 64 + (bg >> 1) * 8 + br;
    const uint32_t bkhalf = (bg & 1) * 16;

    for (int c = 0; c < nchunks; ++c) {
        CP_WAIT1();
        __syncthreads();
        ISSUE_STAGE(c + 2);

        const uint32_t so = smb + (uint32_t)(c % NSTAGE) * ST_BYTES;
        const uint32_t aHb = so, aLb = so + 8192;
        const uint32_t bHb = so + 16384, bLb = so + 24576;

        uint32_t aH[2][2][4], aL[2][2][4];
#pragma unroll
        for (int k16 = 0; k16 < 2; ++k16)
#pragma unroll
            for (int mt = 0; mt < 2; mt++) {
                uint32_t off = sw64((arow0 + mt * 16) * 64 + k16 * 32 + akhalf);
                ldsm4(aH[k16][mt], aHb + off);
                ldsm4(aL[k16][mt], aLb + off);
            }

        uint32_t bH[2][4], bL[2][4];
        {
            uint32_t off0 = sw64(brow0 * 64 + bkhalf);
            ldsm4(bH[0], bHb + off0);
            ldsm4(bL[0], bLb + off0);
        }
#pragma unroll
        for (int s = 0; s < 8; ++s) {
            const int cur = s & 1, nxt = cur ^ 1;
            if (s < 7) {
                const int s1 = s + 1;
                uint32_t off = sw64((brow0 + (s1 & 3) * 16) * 64 +
                                    (s1 >> 2) * 32 + bkhalf);
                ldsm4(bH[nxt], bHb + off);
                ldsm4(bL[nxt], bLb + off);
            }
            const int k16 = s >> 2, nt2 = (s & 3) * 2;
#pragma unroll
            for (int mt = 0; mt < 2; mt++) {
                mma16816(acc[mt][nt2],     aH[k16][mt], &bH[cur][0]);
                mma16816(acc[mt][nt2],     aH[k16][mt], &bL[cur][0]);
                mma16816(acc[mt][nt2],     aL[k16][mt], &bH[cur][0]);
                mma16816(acc[mt][nt2 + 1], aH[k16][mt], &bH[cur][2]);
                mma16816(acc[mt][nt2 + 1], aH[k16][mt], &bL[cur][2]);
                mma16816(acc[mt][nt2 + 1], aL[k16][mt], &bH[cur][2]);
            }
        }
    }
#undef ISSUE_STAGE
    __syncthreads();

    const int rgrp = lane >> 2, cpair = (lane & 3) * 2;
#pragma unroll
    for (int mt = 0; mt < 2; mt++) {
#pragma unroll
        for (int nt = 0; nt < 8; nt++) {
            int row0 = bm + wm * 32 + mt * 16 + rgrp;
            int col = bn + wn * 64 + nt * 8 + cpair;
            float x0 = acc[mt][nt][0], x1 = acc[mt][nt][1];
            float x2 = acc[mt][nt][2], x3 = acc[mt][nt][3];
            if (EPI == 5) {
                size_t o0 = (size_t)z * Cz + (size_t)row0 * xldc + col;
                size_t o1 = o0 + 8ull * xldc;
                uint32_t hh, ll;
                packPair(x0, x1, hh, ll);
                *(uint32_t*)(xCh + o0) = hh; *(uint32_t*)(xCl + o0) = ll;
                packPair(x2, x3, hh, ll);
                *(uint32_t*)(xCh + o1) = hh; *(uint32_t*)(xCl + o1) = ll;
            } else {
                float b0 = 0.f, b1 = 0.f;
                if (EPI == 1) { b0 = bias[col]; b1 = bias[col + 1]; }
                float2 v0, v1;
                v0.x = x0 + b0; v0.y = x1 + b1;
                v1.x = x2 + b0; v1.y = x3 + b1;
                float* Cb = C + (size_t)z * Cz;
                *(float2*)(Cb + (size_t)row0 * ldc + col) = v0;
                *(float2*)(Cb + (size_t)(row0 + 8) * ldc + col) = v1;
            }
        }
    }

    if (EPI == 4) {
        float* redm_ = (float*)sm;              // [128][2]
        float* redsu = (float*)(sm + 1024);     // [128][2]
        __syncthreads();
#pragma unroll
        for (int mt = 0; mt < 2; mt++)
#pragma unroll
            for (int hf = 0; hf < 2; hf++) {
                int lrow = wm * 32 + mt * 16 + hf * 8 + rgrp;
                float mx = -1e30f;
#pragma unroll
                for (int nt = 0; nt < 8; nt++)
                    mx = fmaxf(mx, fmaxf(acc[mt][nt][hf * 2], acc[mt][nt][hf * 2 + 1]));
                mx = fmaxf(mx, __shfl_xor_sync(~0u, mx, 1));
                mx = fmaxf(mx, __shfl_xor_sync(~0u, mx, 2));
                if ((lane & 3) == 0) redm_[lrow * 2 + wn] = mx;
            }
        __syncthreads();
#pragma unroll
        for (int mt = 0; mt < 2; mt++)
#pragma unroll
            for (int hf = 0; hf < 2; hf++) {
                int lrow = wm * 32 + mt * 16 + hf * 8 + rgrp;
                float rm = fmaxf(redm_[lrow * 2], redm_[lrow * 2 + 1]);
                float su = 0.f;
#pragma unroll
                for (int nt = 0; nt < 8; nt++)
                    su += __expf(acc[mt][nt][hf * 2] - rm) +
                          __expf(acc[mt][nt][hf * 2 + 1] - rm);
                su += __shfl_xor_sync(~0u, su, 1);
                su += __shfl_xor_sync(~0u, su, 2);
                if ((lane & 3) == 0) redsu[lrow * 2 + wn] = su;
            }
        __syncthreads();
        if (tid < 128) {
            float m2 = fmaxf(redm_[tid * 2], redm_[tid * 2 + 1]);
            float s2 = redsu[tid * 2] + redsu[tid * 2 + 1];
            size_t o = ((size_t)z * 1024 + bm + tid) * 8 + blockIdx.x;
            g_pmax[o] = m2;
            g_psum[o] = s2;
        }
    }
}

// ================= tensor-core fused flash attention (R14) =================
#define Q_OFF(hl, kc)      ((uint32_t)(((hl) * 2 + (kc)) * 8192))
#define K_OFF(buf, hl, kc) ((uint32_t)(32768 + (buf) * 32768 + ((hl) * 2 + (kc)) * 8192))
#define V_OFF(buf, hl)     ((uint32_t)(98304 + (buf) * 32768 + (hl) * 16384))
#define REDM_OFF 163840
#define MI_OFF   165888
#define IL_OFF   166144
#define ATTN_SMEM (1024 + 166400)

__global__ __launch_bounds__(256, 1) void attn_mma(const float* __restrict__ gl)
{
    extern __shared__ char smraw[];
    uint32_t raw = smem_u32(smraw);
    char* sm = smraw + ((1024u - (raw & 1023u)) & 1023u);
    const uint32_t smb = smem_u32(sm);
    float* mi_s = (float*)(sm + MI_OFF);
    float* il_s = (float*)(sm + IL_OFF);

    const int tid = threadIdx.x, lane = tid & 31, wid = tid >> 5;
    const int wm = wid & 3, wn = wid >> 2;
    const int bg = lane >> 3, br = lane & 7;
    const int i0 = blockIdx.x * 64, h = blockIdx.y, b = blockIdx.z;
    const int bh = b * 8 + h;

    const __nv_bfloat16* qsrc[2] = {
        g_qvh + (size_t)(b * 1024 + i0) * 3072 + h * 128,
        g_qvl + (size_t)(b * 1024 + i0) * 3072 + h * 128 };
    const __nv_bfloat16* ksrc[2] = {
        g_qvh + (size_t)(b * 1024) * 3072 + 1024 + h * 128,
        g_qvl + (size_t)(b * 1024) * 3072 + 1024 + h * 128 };
    const __nv_bfloat16* vsrc[2] = {
        g_qvh + (size_t)(b * 1024) * 3072 + 2048 + h * 128,
        g_qvl + (size_t)(b * 1024) * 3072 + 2048 + h * 128 };
    const float* Sm = g_sm + ((size_t)bh << 20);
    const float* GL = gl + ((size_t)bh << 20);

#define ISSUE_KV(j0_, buf_) do {                                               \
        _Pragma("unroll")                                                      \
        for (int i = 0; i < 8; ++i) {                                          \
            int c = tid + i * 256;                                             \
            int hl = c >> 10, rem = c & 1023;                                  \
            int row = rem >> 4, seg = rem & 15;                                \
            CP16(smb + K_OFF(buf_, hl, seg >> 3) + sw_off(row * 128 + (seg & 7) * 16), \
                 ksrc[hl] + (size_t)((j0_) + row) * 3072 + seg * 8);           \
        }                                                                      \
        _Pragma("unroll")                                                      \
        for (int i = 0; i < 8; ++i) {                                          \
            int c = tid + i * 256;                                             \
            int hl = c >> 10, rem = c & 1023;                                  \
            int row = rem >> 4, seg = rem & 15;                                \
            CP16(smb + V_OFF(buf_, hl) + (seg >> 3) * 8192 + sw_off(row * 128 + (seg & 7) * 16), \
                 vsrc[hl] + (size_t)((j0_) + row) * 3072 + seg * 8);           \
        }                                                                      \
    } while (0)

#pragma unroll
    for (int i = 0; i < 8; ++i) {
        int c = tid + i * 256;
        int hl = c >> 10, rem = c & 1023;
        int row = rem >> 4, seg = rem & 15;
        CP16(smb + Q_OFF(hl, seg >> 3) + sw_off(row * 128 + (seg & 7) * 16),
             qsrc[hl] + (size_t)row * 3072 + seg * 8);
    }
    ISSUE_KV(0, 0);
    CP_COMMIT();

    // ---- fold row-stat combine: this CTA owns rows [i0, i0+64) of bh ----
    if (tid < 64) {
        const float* pm = g_pmax + ((size_t)bh * 1024 + i0 + tid) * 8;
        const float* ps = g_psum + ((size_t)bh * 1024 + i0 + tid) * 8;
        float m = pm[0];
#pragma unroll
        for (int j = 1; j < 8; ++j) m = fmaxf(m, pm[j]);
        float l = 0.f;
#pragma unroll
        for (int j = 0; j < 8; ++j) l += ps[j] * __expf(pm[j] - m);
        mi_s[tid] = m;
        il_s[tid] = 1.f / l;
    }
    __syncthreads();

    const int r0 = wm * 16 + (lane >> 2);
    const float mi0 = mi_s[r0], mi1 = mi_s[r0 + 8];
    const float il0 = il_s[r0], il1 = il_s[r0 + 8];

    float O[16][4];
#pragma unroll
    for (int g = 0; g < 16; g++)
#pragma unroll
        for (int i = 0; i < 4; i++) O[g][i] = 0.f;
    float m_run0 = -1e30f, m_run1 = -1e30f, l_run0 = 0.f, l_run1 = 0.f;

    const uint32_t aRow = (uint32_t)(wm * 16 + (lane & 15)) * 128 + (lane >> 4) * 16;
    const uint32_t bRow0 = (uint32_t)(wn * 32 + (bg >> 1) * 8 + br) * 128 + (bg & 1) * 16;
    const uint32_t bRow1 = bRow0 + 16 * 128;
    const uint32_t vRowBase = (uint32_t)(lane & 15) * 128 + (lane >> 4) * 16;

    for (int jt = 0; jt < 16; ++jt) {
        const int j0 = jt * 64, buf = jt & 1;
        CP_WAIT0();
        __syncthreads();
        if (jt < 15) { ISSUE_KV(j0 + 64, buf ^ 1); CP_COMMIT(); }

        const int colb = j0 + wn * 32 + (lane & 3) * 2;
        float2 smv[4][2], glv[4][2];
#pragma unroll
        for (int nt = 0; nt < 4; nt++) {
            smv[nt][0] = *(const float2*)(Sm + (size_t)(i0 + r0) * 1024 + colb + nt * 8);
            smv[nt][1] = *(const float2*)(Sm + (size_t)(i0 + r0 + 8) * 1024 + colb + nt * 8);
            glv[nt][0] = *(const float2*)(GL + (size_t)(i0 + r0) * 1024 + colb + nt * 8);
            glv[nt][1] = *(const float2*)(GL + (size_t)(i0 + r0 + 8) * 1024 + colb + nt * 8);
        }

        float sc[4][4];
#pragma unroll
        for (int nt = 0; nt < 4; nt++)
#pragma unroll
            for (int i = 0; i < 4; i++) sc[nt][i] = 0.f;

#pragma unroll
        for (int s = 0; s < 8; ++s) {
            const int kc = s >> 2;
            const uint32_t kb = (uint32_t)(s & 3) * 32;
            uint32_t aH[4], aL[4];
            ldsm4(aH, smb + Q_OFF(0, kc) + sw_off(aRow + kb));
            ldsm4(aL, smb + Q_OFF(1, kc) + sw_off(aRow + kb));
            uint32_t kh01[4], kh23[4], kl01[4], kl23[4];
            ldsm4(kh01, smb + K_OFF(buf, 0, kc) + sw_off(bRow0 + kb));
            ldsm4(kh23, smb + K_OFF(buf, 0, kc) + sw_off(bRow1 + kb));
            ldsm4(kl01, smb + K_OFF(buf, 1, kc) + sw_off(bRow0 + kb));
            ldsm4(kl23, smb + K_OFF(buf, 1, kc) + sw_off(bRow1 + kb));
#pragma unroll
            for (int nt = 0; nt < 4; nt++) {
                const uint32_t* bhp = (nt < 2) ? &kh01[(nt & 1) * 2] : &kh23[(nt & 1) * 2];
                const uint32_t* blp = (nt < 2) ? &kl01[(nt & 1) * 2] : &kl23[(nt & 1) * 2];
                mma16816(sc[nt], aH, bhp);
                mma16816(sc[nt], aH, blp);
                mma16816(sc[nt], aL, bhp);
            }
        }

        float mx0 = -1e30f, mx1 = -1e30f;
#pragma unroll
        for (int nt = 0; nt < 4; nt++) {
            float pm0 = __expf(smv[nt][0].x - mi0) * il0;
            float pm1 = __expf(smv[nt][0].y - mi0) * il0;
            float pm2 = __expf(smv[nt][1].x - mi1) * il1;
            float pm3 = __expf(smv[nt][1].y - mi1) * il1;
            sc[nt][0] = fmaf(pm0 * sc[nt][0], SCALE_F, glv[nt][0].x);
            sc[nt][1] = fmaf(pm1 * sc[nt][1], SCALE_F, glv[nt][0].y);
            sc[nt][2] = fmaf(pm2 * sc[nt][2], SCALE_F, glv[nt][1].x);
            sc[nt][3] = fmaf(pm3 * sc[nt][3], SCALE_F, glv[nt][1].y);
            mx0 = fmaxf(mx0, fmaxf(sc[nt][0], sc[nt][1]));
            mx1 = fmaxf(mx1, fmaxf(sc[nt][2], sc[nt][3]));
        }
        mx0 = fmaxf(mx0, __shfl_xor_sync(~0u, mx0, 1));
        mx0 = fmaxf(mx0, __shfl_xor_sync(~0u, mx0, 2));
        mx1 = fmaxf(mx1, __shfl_xor_sync(~0u, mx1, 1));
        mx1 = fmaxf(mx1, __shfl_xor_sync(~0u, mx1, 2));

        float mn0 = fmaxf(m_run0, mx0);
        float mn1 = fmaxf(m_run1, mx1);
        float al0 = __expf(m_run0 - mn0); m_run0 = mn0;
        float al1 = __expf(m_run1 - mn1); m_run1 = mn1;

        float su0 = 0.f, su1 = 0.f;
#pragma unroll
        for (int nt = 0; nt < 4; nt++) {
            sc[nt][0] = __expf(sc[nt][0] - mn0);
            sc[nt][1] = __expf(sc[nt][1] - mn0);
            sc[nt][2] = __expf(sc[nt][2] - mn1);
            sc[nt][3] = __expf(sc[nt][3] - mn1);
            su0 += sc[nt][0] + sc[nt][1];
            su1 += sc[nt][2] + sc[nt][3];
        }
        su0 += __shfl_xor_sync(~0u, su0, 1); su0 += __shfl_xor_sync(~0u, su0, 2);
        su1 += __shfl_xor_sync(~0u, su1, 1); su1 += __shfl_xor_sync(~0u, su1, 2);
        l_run0 = l_run0 * al0 + su0;
        l_run1 = l_run1 * al1 + su1;

        uint32_t aPh[2][4], aPl[2][4];
#pragma unroll
        for (int s = 0; s < 2; s++) {
            packPair(sc[2 * s][0],     sc[2 * s][1],     aPh[s][0], aPl[s][0]);
            packPair(sc[2 * s][2],     sc[2 * s][3],     aPh[s][1], aPl[s][1]);
            packPair(sc[2 * s + 1][0], sc[2 * s + 1][1], aPh[s][2], aPl[s][2]);
            packPair(sc[2 * s + 1][2], sc[2 * s + 1][3], aPh[s][3], aPl[s][3]);
        }

#pragma unroll
        for (int g = 0; g < 16; g++) {
            O[g][0] *= al0; O[g][1] *= al0;
            O[g][2] *= al1; O[g][3] *= al1;
        }

#pragma unroll
        for (int s = 0; s < 2; s++) {
            const uint32_t vro = (uint32_t)(wn * 32 + s * 16) * 128 + vRowBase;
#pragma unroll
            for (int dh = 0; dh < 2; dh++) {
#pragma unroll
                for (int c4 = 0; c4 < 4; c4++) {
                    uint32_t off = sw_off(vro + c4 * 32) + dh * 8192;
                    uint32_t vH[4], vL[4];
                    ldsm4t(vH, smb + V_OFF(buf, 0) + off);
                    ldsm4t(vL, smb + V_OFF(buf, 1) + off);
                    const int g = dh * 8 + c4 * 2;
                    mma16816(O[g],     aPh[s], &vH[0]);
                    mma16816(O[g],     aPh[s], &vL[0]);
                    mma16816(O[g],     aPl[s], &vH[0]);
                    mma16816(O[g + 1], aPh[s], &vH[2]);
                    mma16816(O[g + 1], aPh[s], &vL[2]);
                    mma16816(O[g + 1], aPl[s], &vH[2]);
                }
            }
        }
    }
#undef ISSUE_KV

    // ---- merge the two wn halves: exchange (m,l), exp-scale, sum O --------
    float* mh = (float*)(sm + REDM_OFF);          // [2][128]
    float* lh = (float*)(sm + REDM_OFF + 1024);   // [2][128]
    __syncthreads();
    if ((lane & 3) == 0) {
        mh[wn * 128 + r0] = m_run0;     mh[wn * 128 + r0 + 8] = m_run1;
        lh[wn * 128 + r0] = l_run0;     lh[wn * 128 + r0 + 8] = l_run1;
    }
    __syncthreads();
    float sc0, sc1;
    {
        float ma = mh[r0], mb = mh[128 + r0];
        float M = fmaxf(ma, mb);
        float L = lh[r0] * __expf(ma - M) + lh[128 + r0] * __expf(mb - M);
        sc0 = __expf((wn ? mb : ma) - M) / L;
        float ma1 = mh[r0 + 8], mb1 = mh[128 + r0 + 8];
        float M1 = fmaxf(ma1, mb1);
        float L1 = lh[r0 + 8] * __expf(ma1 - M1) + lh[128 + r0 + 8] * __expf(mb1 - M1);
        sc1 = __expf((wn ? mb1 : ma1) - M1) / L1;
    }

    float* ored = (float*)(sm + 32768);   // aliases K buffers (dead)
    if (wn == 1) {
#pragma unroll
        for (int g = 0; g < 16; g++) {
            *(float2*)&ored[r0 * 132 + g * 8 + (lane & 3) * 2] =
                make_float2(O[g][0] * sc0, O[g][1] * sc0);
            *(float2*)&ored[(r0 + 8) * 132 + g * 8 + (lane & 3) * 2] =
                make_float2(O[g][2] * sc1, O[g][3] * sc1);
        }
    }
    __syncthreads();
    if (wn == 0) {
#pragma unroll
        for (int g = 0; g < 16; g++) {
            float2 a0 = *(float2*)&ored[r0 * 132 + g * 8 + (lane & 3) * 2];
            float2 a1 = *(float2*)&ored[(r0 + 8) * 132 + g * 8 + (lane & 3) * 2];
            float x0 = O[g][0] * sc0 + a0.x;
            float x1 = O[g][1] * sc0 + a0.y;
            float x2 = O[g][2] * sc1 + a1.x;
            float x3 = O[g][3] * sc1 + a1.y;
            uint32_t hh, ll;
            size_t off = (size_t)(b * 1024 + i0 + r0) * 1024 + h * 128 + g * 8 + (lane & 3) * 2;
            packPair(x0, x1, hh, ll);
            *(uint32_t*)(g_aoh + off) = hh; *(uint32_t*)(g_aol + off) = ll;
            packPair(x2, x3, hh, ll);
            *(uint32_t*)(g_aoh + off + 8 * 1024) = hh;
            *(uint32_t*)(g_aol + off + 8 * 1024) = ll;
        }
    }
}

// ---------------- launch ----------------------------------------------------
extern "C" void kernel_launch(void* const* d_in, const int* in_sizes, int n_in,
                              void* d_out, int out_size)
{
    const float* s_v   = (const float*)d_in[0];
    const float* s_m   = (const float*)d_in[1];
    const float* g_l   = (const float*)d_in[2];
    const float* W_qkv = (const float*)d_in[3];
    const float* W_qk  = (const float*)d_in[4];
    const float* W_out = (const float*)d_in[5];
    const float* b_out = (const float*)d_in[6];
    float* out = (float*)d_out;

    float* p_sm;
    __nv_bfloat16 *p_wouth, *p_woutl, *p_qkh, *p_qkl, *p_aoh, *p_aol;
    cudaGetSymbolAddress((void**)&p_sm,  g_sm);
    cudaGetSymbolAddress((void**)&p_wouth, g_wouth);
    cudaGetSymbolAddress((void**)&p_woutl, g_woutl);
    cudaGetSymbolAddress((void**)&p_qkh, g_qkh);
    cudaGetSymbolAddress((void**)&p_qkl, g_qkl);
    cudaGetSymbolAddress((void**)&p_aoh, g_aoh);
    cudaGetSymbolAddress((void**)&p_aol, g_aol);

    cudaFuncSetAttribute(gemm_bf16<1>, cudaFuncAttributeMaxDynamicSharedMemorySize, GEMM_SMEM);
    cudaFuncSetAttribute(gemm_bf16<4>, cudaFuncAttributeMaxDynamicSharedMemorySize, GEMM_SMEM);
    cudaFuncSetAttribute(gemm_bf16<5>, cudaFuncAttributeMaxDynamicSharedMemorySize, GEMM_SMEM);
    cudaFuncSetAttribute(attn_mma, cudaFuncAttributeMaxDynamicSharedMemorySize, ATTN_SMEM);

    // [0] ALL preprocessing in one launch (activations + weights)
    prep_all<<<14336, 256>>>((const float4*)s_v, (const float4*)s_m,
                             W_qkv, W_qk, W_out);
    // [1] FUSED QKV + QK projections
    gemm_bf16<5><<<dim3(40, 64, 1), 256, GEMM_SMEM>>>(
        nullptr, nullptr, 1024, 0, 0, nullptr, nullptr, 1024, 0, 0,
        nullptr, nullptr, nullptr, 3072, 0, 1024, nullptr);
    // [2] m-stream scores per (b,h) -> fp32 g_sm + fused row-stat partials
    gemm_bf16<4><<<dim3(8, 8, 64), 256, GEMM_SMEM>>>(
        p_qkh, p_qkl, 2048, (size_t)NN * 2048, 128,
        p_qkh + 1024, p_qkl + 1024, 2048, (size_t)NN * 2048, 128,
        p_sm, nullptr, nullptr, 1024, (size_t)NN * NN, 128, nullptr);
    // [3] tensor-core fused attention (row-stat combine folded in)
    attn_mma<<<dim3(16, NH, NB), 256, ATTN_SMEM>>>(g_l);
    // [4] output projection + bias -> out
    gemm_bf16<1><<<dim3(8, 64, 1), 256, GEMM_SMEM>>>(
        p_aoh, p_aol, 1024, 0, 0, p_wouth, p_woutl, 1024, 0, 0,
        out, nullptr, nullptr, 1024, 0, 1024, b_out);
}